// round 6
// baseline (speedup 1.0000x reference)
#include <cuda_runtime.h>

// SpecEMA single-pass decoupled-lookback scan.
// x staged in SMEM (read once), float4, plain LDG/STG (no cache hints),
// 32-bit indexing, 8 blocks/SM. Generation-coded flags (no reset kernel).
#define BB 64
#define CC 2
#define TT 4000
#define FF 96
#define NF4 24               // FF/4
#define NSUB 8
#define LS 4
#define LCH (NSUB * LS)      // 32
#define NCH (TT / LCH)       // 125
#define NTHR (NSUB * NF4)    // 192
#define GRID (BB * NCH)      // 8000

#define ALPHA_F 0.99f
#define OMA_F ((float)(1.0 - 0.99))   // float32(1 - 0.99), matches jax

__host__ __device__ constexpr float fpow(float a, int n) {
    float r = 1.0f;
    for (int i = 0; i < n; i++) r *= a;
    return r;
}

// ---- scratch (__device__ globals; allocation-free rule; zero-initialized) ----
__device__ float4 g_agg[GRID * NF4];
__device__ float4 g_inc[GRID * NF4];
__device__ unsigned g_flag[GRID];    // gen-coded: 2*gen+1 = agg, 2*gen+2 = inc
__device__ unsigned g_ctr;           // monotone across graph replays

__device__ __forceinline__ unsigned ld_acquire(const unsigned* p) {
    unsigned v;
    asm volatile("ld.global.acquire.gpu.b32 %0, [%1];" : "=r"(v) : "l"(p));
    return v;
}
__device__ __forceinline__ void st_release(unsigned* p, unsigned v) {
    asm volatile("st.global.release.gpu.b32 [%0], %1;" :: "l"(p), "r"(v));
}

#define EMA4(s, a, c)                                                        \
    (s).x = fmaf(fmaf((a).x, (a).x, (c).x * (c).x), OMA_F, (s).x * ALPHA_F); \
    (s).y = fmaf(fmaf((a).y, (a).y, (c).y * (c).y), OMA_F, (s).y * ALPHA_F); \
    (s).z = fmaf(fmaf((a).z, (a).z, (c).z * (c).z), OMA_F, (s).z * ALPHA_F); \
    (s).w = fmaf(fmaf((a).w, (a).w, (c).w * (c).w), OMA_F, (s).w * ALPHA_F)

#define FMA4(acc, w, v)                  \
    (acc).x = fmaf((w), (v).x, (acc).x); \
    (acc).y = fmaf((w), (v).y, (acc).y); \
    (acc).z = fmaf((w), (v).z, (acc).z); \
    (acc).w = fmaf((w), (v).w, (acc).w)

#define FOLD4(s, aLS, P)                 \
    (s).x = fmaf((aLS), (s).x, (P).x);   \
    (s).y = fmaf((aLS), (s).y, (P).y);   \
    (s).z = fmaf((aLS), (s).z, (P).z);   \
    (s).w = fmaf((aLS), (s).w, (P).w)

__global__ void __launch_bounds__(NTHR, 8)
k_scan(const float* __restrict__ x,
       const float* __restrict__ state,
       float* __restrict__ out,
       float* __restrict__ fstate,
       int write_state) {
    __shared__ float4 xs[LCH][CC][NF4];   // 24576 B
    __shared__ float4 sP[NSUB][NF4];      //  3072 B
    __shared__ unsigned s_vbid;

    const int tid = threadIdx.x;
    if (tid == 0) s_vbid = atomicAdd(&g_ctr, 1u);
    __syncthreads();
    const unsigned raw = s_vbid;
    const unsigned gen = raw / (unsigned)GRID;
    const int vbid = (int)(raw % (unsigned)GRID);
    const unsigned V_AGG = 2u * gen + 1u;
    const unsigned V_INC = 2u * gen + 2u;

    const int b   = vbid % BB;        // b fastest: predecessors scheduled first
    const int j   = vbid / BB;
    const int f4  = tid % NF4;
    const int sub = tid / NF4;

    const float aLS = fpow(ALPHA_F, LS);    // alpha^4
    const float aB  = fpow(ALPHA_F, LCH);   // alpha^32

    // 32-bit element offsets (total 49.2M < 2^31)
    const int e0 = ((b * CC + 0) * TT + j * LCH + sub * LS) * FF + f4 * 4;
    const int e1 = ((b * CC + 1) * TT + j * LCH + sub * LS) * FF + f4 * 4;
    const float4* p0 = (const float4*)(x + e0);   // time stride = NF4 float4
    const float4* p1 = (const float4*)(x + e1);

    // ---- phase 1: stream x chunk into SMEM, per-sub partial EMA from s=0 ----
    float4 P = make_float4(0.f, 0.f, 0.f, 0.f);
#pragma unroll
    for (int t = 0; t < LS; t++) {
        float4 a = p0[t * NF4];
        float4 c = p1[t * NF4];
        xs[sub * LS + t][0][f4] = a;
        xs[sub * LS + t][1][f4] = c;
        EMA4(P, a, c);
    }
    sP[sub][f4] = P;
    __syncthreads();

    // block aggregate
    float4 A = sP[0][f4];
#pragma unroll
    for (int k = 1; k < NSUB; k++) {
        float4 t4 = sP[k][f4];
        FOLD4(A, aLS, t4);
    }

    const int chain = b * NCH + j;
    if (sub == 0) {                     // tids 0..23, all in warp 0
        g_agg[chain * NF4 + f4] = A;
        __syncwarp(0x00FFFFFFu);
        if (tid == 0) { __threadfence(); st_release(&g_flag[chain], V_AGG); }
    }

    // ---- phase 2: barrier-free lookback ----
    float4 S;
    if (j == 0) {
        S = *(const float4*)(state + f4 * 4);
    } else {
        float4 acc = make_float4(0.f, 0.f, 0.f, 0.f);
        float w = 1.0f;
        int k = j - 1;
        for (;;) {
            const unsigned* fl = &g_flag[b * NCH + k];
            unsigned st = ld_acquire(fl);
            int spins = 0;
            while (st < V_AGG) {                 // stale generation == empty
                if (++spins > 8) { __nanosleep(128); spins = 0; }
                st = ld_acquire(fl);
            }
            if (st == V_INC) {
                float4 v = g_inc[(b * NCH + k) * NF4 + f4];
                FMA4(acc, w, v);
                break;
            }
            float4 v = g_agg[(b * NCH + k) * NF4 + f4];
            FMA4(acc, w, v);
            w *= aB;
            if (k == 0) {
                float4 s0 = *(const float4*)(state + f4 * 4);
                FMA4(acc, w, s0);
                break;
            }
            k--;
        }
        S = acc;
    }

    // ---- publish inclusive ASAP ----
    if (sub == 0) {
        float4 inc;
        inc.x = fmaf(aB, S.x, A.x);
        inc.y = fmaf(aB, S.y, A.y);
        inc.z = fmaf(aB, S.z, A.z);
        inc.w = fmaf(aB, S.w, A.w);
        g_inc[chain * NF4 + f4] = inc;
        __syncwarp(0x00FFFFFFu);
        if (tid == 0) { __threadfence(); st_release(&g_flag[chain], V_INC); }
    }

    // ---- start state for this sub-chunk ----
    float4 s4 = S;
#pragma unroll
    for (int k = 0; k < NSUB - 1; k++) {
        if (k < sub) {
            float4 Pk = sP[k][f4];
            FOLD4(s4, aLS, Pk);
        }
    }

    // ---- phase 3: replay from SMEM, write outputs ----
    float4* o0 = (float4*)(out + e0);
    float4* o1 = (float4*)(out + e1);
#pragma unroll
    for (int t = 0; t < LS; t++) {
        float4 a = xs[sub * LS + t][0][f4];
        float4 c = xs[sub * LS + t][1][f4];
        EMA4(s4, a, c);
        float4 r;
        r.x = rsqrtf(s4.x); r.y = rsqrtf(s4.y);
        r.z = rsqrtf(s4.z); r.w = rsqrtf(s4.w);
        float4 y0, y1;
        y0.x = a.x * r.x; y0.y = a.y * r.y; y0.z = a.z * r.z; y0.w = a.w * r.w;
        y1.x = c.x * r.x; y1.y = c.y * r.y; y1.z = c.z * r.z; y1.w = c.w * r.w;
        o0[t * NF4] = y0;
        o1[t * NF4] = y1;
    }

    if (write_state && j == NCH - 1 && sub == NSUB - 1) {
        *(float4*)(fstate + b * FF + f4 * 4) = s4;
    }
}

extern "C" void kernel_launch(void* const* d_in, const int* in_sizes, int n_in,
                              void* d_out, int out_size) {
    const float* feat  = (const float*)d_in[0];   // [B,C,T,F] f32
    const float* state = (const float*)d_in[1];   // [1,1,F]   f32
    float* out = (float*)d_out;

    const int n_out_main = BB * CC * TT * FF;     // 49,152,000
    int write_state = (out_size >= n_out_main + BB * FF) ? 1 : 0;
    float* fstate = out + n_out_main;

    k_scan<<<GRID, NTHR>>>(feat, state, out, fstate, write_state);
}

// round 7
// speedup vs baseline: 1.0080x; 1.0080x over previous
#include <cuda_runtime.h>

// SpecEMA single-pass decoupled-lookback scan, 2 adjacent chunks per block.
// One lookback per 2 chunks; chunk-1 load overlaps chunk-0 publish latency.
#define BB 64
#define CC 2
#define TT 4000
#define FF 96
#define NF4 24               // FF/4
#define NSUB 8
#define LS 5
#define LCH (NSUB * LS)      // 40
#define NCH (TT / LCH)       // 100 chains
#define NPB 2                // chunks per block
#define NTHR (NSUB * NF4)    // 192
#define GRIDB (BB * NCH / NPB)  // 3200

#define ALPHA_F 0.99f
#define OMA_F ((float)(1.0 - 0.99))   // float32(1 - 0.99), matches jax

__host__ __device__ constexpr float fpow(float a, int n) {
    float r = 1.0f;
    for (int i = 0; i < n; i++) r *= a;
    return r;
}

// ---- scratch (__device__ globals; allocation-free; zero-initialized) ----
__device__ float4 g_agg[BB * NCH * NF4];
__device__ float4 g_inc[BB * NCH * NF4];
__device__ unsigned g_flag[BB * NCH];  // gen-coded: 2*gen+1 = agg, 2*gen+2 = inc
__device__ unsigned g_ctr;             // monotone across graph replays

__device__ __forceinline__ unsigned ld_acquire(const unsigned* p) {
    unsigned v;
    asm volatile("ld.global.acquire.gpu.b32 %0, [%1];" : "=r"(v) : "l"(p));
    return v;
}
__device__ __forceinline__ void st_release(unsigned* p, unsigned v) {
    asm volatile("st.global.release.gpu.b32 [%0], %1;" :: "l"(p), "r"(v));
}

#define EMA4(s, a, c)                                                        \
    (s).x = fmaf(fmaf((a).x, (a).x, (c).x * (c).x), OMA_F, (s).x * ALPHA_F); \
    (s).y = fmaf(fmaf((a).y, (a).y, (c).y * (c).y), OMA_F, (s).y * ALPHA_F); \
    (s).z = fmaf(fmaf((a).z, (a).z, (c).z * (c).z), OMA_F, (s).z * ALPHA_F); \
    (s).w = fmaf(fmaf((a).w, (a).w, (c).w * (c).w), OMA_F, (s).w * ALPHA_F)

#define FMA4(acc, w, v)                  \
    (acc).x = fmaf((w), (v).x, (acc).x); \
    (acc).y = fmaf((w), (v).y, (acc).y); \
    (acc).z = fmaf((w), (v).z, (acc).z); \
    (acc).w = fmaf((w), (v).w, (acc).w)

#define FOLD4(s, aLS, P)                 \
    (s).x = fmaf((aLS), (s).x, (P).x);   \
    (s).y = fmaf((aLS), (s).y, (P).y);   \
    (s).z = fmaf((aLS), (s).z, (P).z);   \
    (s).w = fmaf((aLS), (s).w, (P).w)

__global__ void __launch_bounds__(NTHR, 3)
k_scan(const float* __restrict__ x,
       const float* __restrict__ state,
       float* __restrict__ out,
       float* __restrict__ fstate,
       int write_state) {
    __shared__ float4 xs[NPB][LCH][CC][NF4];   // 61440 B
    __shared__ float4 sP[NPB][NSUB][NF4];      //  6144 B
    __shared__ unsigned s_vbid;

    const int tid = threadIdx.x;
    if (tid == 0) s_vbid = atomicAdd(&g_ctr, 1u);
    __syncthreads();
    const unsigned raw = s_vbid;
    const unsigned gen = raw / (unsigned)GRIDB;
    const int vbid = (int)(raw % (unsigned)GRIDB);
    const unsigned V_AGG = 2u * gen + 1u;
    const unsigned V_INC = 2u * gen + 2u;

    const int b  = vbid % BB;          // b fastest: predecessors scheduled first
    const int m  = vbid / BB;          // pair index
    const int j0 = 2 * m;
    const int f4  = tid % NF4;
    const int sub = tid / NF4;

    const float aLS = fpow(ALPHA_F, LS);    // alpha^5
    const float aB  = fpow(ALPHA_F, LCH);   // alpha^40

    // element offsets (32-bit; total < 2^31)
    const int base0 = ((b * CC + 0) * TT) * FF;
    const int base1 = ((b * CC + 1) * TT) * FF;

    const int chain0 = b * NCH + j0;
    const int chain1 = chain0 + 1;

    float4 A[NPB];

    // ---- phase 1: load both chunks, publish aggregates as they complete ----
#pragma unroll
    for (int q = 0; q < NPB; q++) {
        const int toff = (j0 + q) * LCH + sub * LS;
        const float4* p0 = (const float4*)(x + base0 + toff * FF) + f4;
        const float4* p1 = (const float4*)(x + base1 + toff * FF) + f4;
        float4 P = make_float4(0.f, 0.f, 0.f, 0.f);
#pragma unroll
        for (int t = 0; t < LS; t++) {
            float4 a = p0[t * NF4];
            float4 c = p1[t * NF4];
            xs[q][sub * LS + t][0][f4] = a;
            xs[q][sub * LS + t][1][f4] = c;
            EMA4(P, a, c);
        }
        sP[q][sub][f4] = P;
        __syncthreads();
        // fold block aggregate for chunk q
        float4 Aq = sP[q][0][f4];
#pragma unroll
        for (int k = 1; k < NSUB; k++) {
            float4 t4 = sP[q][k][f4];
            FOLD4(Aq, aLS, t4);
        }
        A[q] = Aq;
        if (sub == 0) {                 // tids 0..23 (warp 0)
            g_agg[(chain0 + q) * NF4 + f4] = Aq;
            __syncwarp(0x00FFFFFFu);
            if (tid == 0) { __threadfence(); st_release(&g_flag[chain0 + q], V_AGG); }
        }
    }

    // ---- phase 2: ONE barrier-free lookback for chunk j0 ----
    float4 S0;
    if (j0 == 0) {
        S0 = *(const float4*)(state + f4 * 4);
    } else {
        float4 acc = make_float4(0.f, 0.f, 0.f, 0.f);
        float w = 1.0f;
        int k = j0 - 1;
        for (;;) {
            const unsigned* fl = &g_flag[b * NCH + k];
            unsigned st = ld_acquire(fl);
            int spins = 0;
            while (st < V_AGG) {             // stale generation == empty
                if (++spins > 8) { __nanosleep(128); spins = 0; }
                st = ld_acquire(fl);
            }
            if (st == V_INC) {
                float4 v = g_inc[(b * NCH + k) * NF4 + f4];
                FMA4(acc, w, v);
                break;
            }
            float4 v = g_agg[(b * NCH + k) * NF4 + f4];
            FMA4(acc, w, v);
            w *= aB;
            if (k == 0) {
                float4 s0 = *(const float4*)(state + f4 * 4);
                FMA4(acc, w, s0);
                break;
            }
            k--;
        }
        S0 = acc;
    }

    // ---- publish both inclusives ASAP (before any stores) ----
    float4 S1;  // start state of chunk j0+1 = inclusive of j0
    S1.x = fmaf(aB, S0.x, A[0].x);
    S1.y = fmaf(aB, S0.y, A[0].y);
    S1.z = fmaf(aB, S0.z, A[0].z);
    S1.w = fmaf(aB, S0.w, A[0].w);
    if (sub == 0) {
        g_inc[chain0 * NF4 + f4] = S1;
        float4 inc1;
        inc1.x = fmaf(aB, S1.x, A[1].x);
        inc1.y = fmaf(aB, S1.y, A[1].y);
        inc1.z = fmaf(aB, S1.z, A[1].z);
        inc1.w = fmaf(aB, S1.w, A[1].w);
        g_inc[chain1 * NF4 + f4] = inc1;
        __syncwarp(0x00FFFFFFu);
        if (tid == 0) {
            __threadfence();
            st_release(&g_flag[chain0], V_INC);
            st_release(&g_flag[chain1], V_INC);
        }
    }

    // ---- phase 3: replay both chunks from SMEM, write outputs ----
#pragma unroll
    for (int q = 0; q < NPB; q++) {
        float4 s4 = (q == 0) ? S0 : S1;
        // advance to this thread's sub-chunk start
#pragma unroll
        for (int k = 0; k < NSUB - 1; k++) {
            if (k < sub) {
                float4 Pk = sP[q][k][f4];
                FOLD4(s4, aLS, Pk);
            }
        }
        const int toff = (j0 + q) * LCH + sub * LS;
        float4* o0 = (float4*)(out + base0 + toff * FF) + f4;
        float4* o1 = (float4*)(out + base1 + toff * FF) + f4;
#pragma unroll
        for (int t = 0; t < LS; t++) {
            float4 a = xs[q][sub * LS + t][0][f4];
            float4 c = xs[q][sub * LS + t][1][f4];
            EMA4(s4, a, c);
            float4 r;
            r.x = rsqrtf(s4.x); r.y = rsqrtf(s4.y);
            r.z = rsqrtf(s4.z); r.w = rsqrtf(s4.w);
            float4 y0, y1;
            y0.x = a.x * r.x; y0.y = a.y * r.y; y0.z = a.z * r.z; y0.w = a.w * r.w;
            y1.x = c.x * r.x; y1.y = c.y * r.y; y1.z = c.z * r.z; y1.w = c.w * r.w;
            o0[t * NF4] = y0;
            o1[t * NF4] = y1;
        }
        if (write_state && (j0 + q) == NCH - 1 && sub == NSUB - 1) {
            *(float4*)(fstate + b * FF + f4 * 4) = s4;
        }
    }
}

extern "C" void kernel_launch(void* const* d_in, const int* in_sizes, int n_in,
                              void* d_out, int out_size) {
    const float* feat  = (const float*)d_in[0];   // [B,C,T,F] f32
    const float* state = (const float*)d_in[1];   // [1,1,F]   f32
    float* out = (float*)d_out;

    const int n_out_main = BB * CC * TT * FF;     // 49,152,000
    int write_state = (out_size >= n_out_main + BB * FF) ? 1 : 0;
    float* fstate = out + n_out_main;

    k_scan<<<GRIDB, NTHR>>>(feat, state, out, fstate, write_state);
}

// round 8
// speedup vs baseline: 1.1720x; 1.1627x over previous
#include <cuda_runtime.h>
#include <cstdint>

// SpecEMA single-pass decoupled-lookback scan with TMA bulk copies.
// x tile: cp.async.bulk g->s (one issue, 30KB in flight). y computed in-place
// in smem, stored by cp.async.bulk s->g (fire-and-forget). Warps never issue
// LDG/STG for the bulk data. Generation-coded flags (no reset kernel).
#define BB 64
#define CC 2
#define TT 4000
#define FF 96
#define NF4 24               // FF/4
#define NSUB 8
#define LS 5
#define LCH (NSUB * LS)      // 40
#define NCH (TT / LCH)       // 100
#define NTHR (NSUB * NF4)    // 192
#define GRID (BB * NCH)      // 6400
#define TILE_C_BYTES (LCH * FF * 4)      // 15360 (contiguous per channel)

#define ALPHA_F 0.99f
#define OMA_F ((float)(1.0 - 0.99))   // float32(1 - 0.99), matches jax

__host__ __device__ constexpr float fpow(float a, int n) {
    float r = 1.0f;
    for (int i = 0; i < n; i++) r *= a;
    return r;
}

// ---- scratch (__device__ globals; allocation-free; zero-initialized) ----
__device__ float4 g_agg[GRID * NF4];
__device__ float4 g_inc[GRID * NF4];
__device__ unsigned g_flag[GRID];    // gen-coded: 2*gen+1 = agg, 2*gen+2 = inc
__device__ unsigned g_ctr;           // monotone across graph replays

__device__ __forceinline__ unsigned ld_acquire(const unsigned* p) {
    unsigned v;
    asm volatile("ld.global.acquire.gpu.b32 %0, [%1];" : "=r"(v) : "l"(p));
    return v;
}
__device__ __forceinline__ void st_release(unsigned* p, unsigned v) {
    asm volatile("st.global.release.gpu.b32 [%0], %1;" :: "l"(p), "r"(v));
}
__device__ __forceinline__ uint32_t smem_u32(const void* p) {
    return (uint32_t)__cvta_generic_to_shared(p);
}
__device__ __forceinline__ void mbar_init(uint32_t mbar, uint32_t cnt) {
    asm volatile("mbarrier.init.shared.b64 [%0], %1;" :: "r"(mbar), "r"(cnt) : "memory");
}
__device__ __forceinline__ void mbar_expect_tx(uint32_t mbar, uint32_t bytes) {
    asm volatile("mbarrier.arrive.expect_tx.shared.b64 _, [%0], %1;"
                 :: "r"(mbar), "r"(bytes) : "memory");
}
__device__ __forceinline__ void mbar_wait_parity0(uint32_t mbar) {
    asm volatile(
        "{\n\t.reg .pred P1;\n\t"
        "WAIT_LOOP_%=:\n\t"
        "mbarrier.try_wait.parity.acquire.cta.shared::cta.b64 P1, [%0], 0, 0x989680;\n\t"
        "@P1 bra.uni WAIT_DONE_%=;\n\t"
        "bra.uni WAIT_LOOP_%=;\n\t"
        "WAIT_DONE_%=:\n\t}"
        :: "r"(mbar) : "memory");
}
__device__ __forceinline__ void bulk_ld(uint32_t smem_dst, const void* gsrc,
                                        uint32_t bytes, uint32_t mbar) {
    asm volatile("cp.async.bulk.shared::cta.global.mbarrier::complete_tx::bytes "
                 "[%0], [%1], %2, [%3];"
                 :: "r"(smem_dst), "l"(gsrc), "r"(bytes), "r"(mbar) : "memory");
}
__device__ __forceinline__ void bulk_st(void* gdst, uint32_t smem_src, uint32_t bytes) {
    asm volatile("cp.async.bulk.global.shared::cta.bulk_group [%0], [%1], %2;"
                 :: "l"(gdst), "r"(smem_src), "r"(bytes) : "memory");
}

#define EMA4(s, a, c)                                                        \
    (s).x = fmaf(fmaf((a).x, (a).x, (c).x * (c).x), OMA_F, (s).x * ALPHA_F); \
    (s).y = fmaf(fmaf((a).y, (a).y, (c).y * (c).y), OMA_F, (s).y * ALPHA_F); \
    (s).z = fmaf(fmaf((a).z, (a).z, (c).z * (c).z), OMA_F, (s).z * ALPHA_F); \
    (s).w = fmaf(fmaf((a).w, (a).w, (c).w * (c).w), OMA_F, (s).w * ALPHA_F)

#define FMA4(acc, w, v)                  \
    (acc).x = fmaf((w), (v).x, (acc).x); \
    (acc).y = fmaf((w), (v).y, (acc).y); \
    (acc).z = fmaf((w), (v).z, (acc).z); \
    (acc).w = fmaf((w), (v).w, (acc).w)

#define FOLD4(s, aLS, P)                 \
    (s).x = fmaf((aLS), (s).x, (P).x);   \
    (s).y = fmaf((aLS), (s).y, (P).y);   \
    (s).z = fmaf((aLS), (s).z, (P).z);   \
    (s).w = fmaf((aLS), (s).w, (P).w)

__global__ void __launch_bounds__(NTHR, 6)
k_scan(const float* __restrict__ x,
       const float* __restrict__ state,
       float* __restrict__ out,
       float* __restrict__ fstate,
       int write_state) {
    // c-major tile so each channel is one contiguous 15360B bulk-copy region
    __shared__ alignas(128) float4 xs[CC][LCH][NF4];   // 30720 B
    __shared__ float4 sP[NSUB][NF4];                   //  3072 B
    __shared__ uint64_t mbar;
    __shared__ unsigned s_vbid;

    const int tid = threadIdx.x;
    const uint32_t mb = smem_u32(&mbar);
    if (tid == 0) {
        s_vbid = atomicAdd(&g_ctr, 1u);
        mbar_init(mb, 1);
    }
    __syncthreads();
    const unsigned raw = s_vbid;
    const unsigned gen = raw / (unsigned)GRID;
    const int vbid = (int)(raw % (unsigned)GRID);
    const unsigned V_AGG = 2u * gen + 1u;
    const unsigned V_INC = 2u * gen + 2u;

    const int b   = vbid % BB;        // b fastest: predecessors scheduled first
    const int j   = vbid / BB;
    const int f4  = tid % NF4;
    const int sub = tid / NF4;

    // global bases (elements); each (c) slice of the chunk is contiguous
    const int g0 = ((b * CC + 0) * TT + j * LCH) * FF;
    const int g1 = ((b * CC + 1) * TT + j * LCH) * FF;

    // ---- phase 0: one thread launches both bulk loads ----
    if (tid == 0) {
        mbar_expect_tx(mb, 2 * TILE_C_BYTES);
        bulk_ld(smem_u32(&xs[0][0][0]), x + g0, TILE_C_BYTES, mb);
        bulk_ld(smem_u32(&xs[1][0][0]), x + g1, TILE_C_BYTES, mb);
    }

    const float aLS = fpow(ALPHA_F, LS);    // alpha^5
    const float aB  = fpow(ALPHA_F, LCH);   // alpha^40

    mbar_wait_parity0(mb);

    // ---- phase 1: per-sub partial EMA from s=0 (smem reads) ----
    float4 P = make_float4(0.f, 0.f, 0.f, 0.f);
#pragma unroll
    for (int t = 0; t < LS; t++) {
        float4 a = xs[0][sub * LS + t][f4];
        float4 c = xs[1][sub * LS + t][f4];
        EMA4(P, a, c);
    }
    sP[sub][f4] = P;
    __syncthreads();

    // block aggregate
    float4 A = sP[0][f4];
#pragma unroll
    for (int k = 1; k < NSUB; k++) {
        float4 t4 = sP[k][f4];
        FOLD4(A, aLS, t4);
    }

    const int chain = b * NCH + j;
    if (sub == 0) {                     // tids 0..23, warp 0
        g_agg[chain * NF4 + f4] = A;
        __syncwarp(0x00FFFFFFu);
        if (tid == 0) { __threadfence(); st_release(&g_flag[chain], V_AGG); }
    }

    // ---- phase 2: barrier-free lookback ----
    float4 S;
    if (j == 0) {
        S = *(const float4*)(state + f4 * 4);
    } else {
        float4 acc = make_float4(0.f, 0.f, 0.f, 0.f);
        float w = 1.0f;
        int k = j - 1;
        for (;;) {
            const unsigned* fl = &g_flag[b * NCH + k];
            unsigned st = ld_acquire(fl);
            int spins = 0;
            while (st < V_AGG) {                 // stale generation == empty
                if (++spins > 8) { __nanosleep(128); spins = 0; }
                st = ld_acquire(fl);
            }
            if (st == V_INC) {
                float4 v = g_inc[(b * NCH + k) * NF4 + f4];
                FMA4(acc, w, v);
                break;
            }
            float4 v = g_agg[(b * NCH + k) * NF4 + f4];
            FMA4(acc, w, v);
            w *= aB;
            if (k == 0) {
                float4 s0 = *(const float4*)(state + f4 * 4);
                FMA4(acc, w, s0);
                break;
            }
            k--;
        }
        S = acc;
    }

    // ---- publish inclusive ASAP ----
    if (sub == 0) {
        float4 inc;
        inc.x = fmaf(aB, S.x, A.x);
        inc.y = fmaf(aB, S.y, A.y);
        inc.z = fmaf(aB, S.z, A.z);
        inc.w = fmaf(aB, S.w, A.w);
        g_inc[chain * NF4 + f4] = inc;
        __syncwarp(0x00FFFFFFu);
        if (tid == 0) { __threadfence(); st_release(&g_flag[chain], V_INC); }
    }

    // ---- start state for this sub-chunk ----
    float4 s4 = S;
#pragma unroll
    for (int k = 0; k < NSUB - 1; k++) {
        if (k < sub) {
            float4 Pk = sP[k][f4];
            FOLD4(s4, aLS, Pk);
        }
    }

    // ---- phase 3: replay, compute y IN PLACE in smem ----
#pragma unroll
    for (int t = 0; t < LS; t++) {
        float4 a = xs[0][sub * LS + t][f4];
        float4 c = xs[1][sub * LS + t][f4];
        EMA4(s4, a, c);
        float4 r;
        r.x = rsqrtf(s4.x); r.y = rsqrtf(s4.y);
        r.z = rsqrtf(s4.z); r.w = rsqrtf(s4.w);
        float4 y0, y1;
        y0.x = a.x * r.x; y0.y = a.y * r.y; y0.z = a.z * r.z; y0.w = a.w * r.w;
        y1.x = c.x * r.x; y1.y = c.y * r.y; y1.z = c.z * r.z; y1.w = c.w * r.w;
        xs[0][sub * LS + t][f4] = y0;
        xs[1][sub * LS + t][f4] = y1;
    }

    if (write_state && j == NCH - 1 && sub == NSUB - 1) {
        *(float4*)(fstate + b * FF + f4 * 4) = s4;
    }

    __syncthreads();
    // order generic-proxy smem writes before async-proxy bulk store
    asm volatile("fence.proxy.async.shared::cta;" ::: "memory");
    if (tid == 0) {
        bulk_st(out + g0, smem_u32(&xs[0][0][0]), TILE_C_BYTES);
        bulk_st(out + g1, smem_u32(&xs[1][0][0]), TILE_C_BYTES);
        asm volatile("cp.async.bulk.commit_group;" ::: "memory");
        // must complete before CTA teardown frees smem
        asm volatile("cp.async.bulk.wait_group 0;" ::: "memory");
    }
}

extern "C" void kernel_launch(void* const* d_in, const int* in_sizes, int n_in,
                              void* d_out, int out_size) {
    const float* feat  = (const float*)d_in[0];   // [B,C,T,F] f32
    const float* state = (const float*)d_in[1];   // [1,1,F]   f32
    float* out = (float*)d_out;

    const int n_out_main = BB * CC * TT * FF;     // 49,152,000
    int write_state = (out_size >= n_out_main + BB * FF) ? 1 : 0;
    float* fstate = out + n_out_main;

    k_scan<<<GRID, NTHR>>>(feat, state, out, fstate, write_state);
}